// round 12
// baseline (speedup 1.0000x reference)
#include <cuda_runtime.h>
#include <cuda_fp16.h>
#include <cstdint>

// TransitionLayer: BN(eval)+ReLU+1x1conv(512->256)+avgpool2x2, NCHW fp32.
// pool(conv(act)) == conv(pool(act)) -> GEMM M=50176, K=512, N=256.
// R12: cp.async producer. Raw fp32 x copied to a 2-stage smem ring via
//      cp.async.cg (latency off the register graph); converter does
//      BN+ReLU+pool from smem (LDS.128, quad-shifted conflict-free layout)
//      -> fp16 A tile. Consumer = R11 (64m x 32n, B reg pipeline, 1-term fp16).

#define BN_EPS 1e-5f

constexpr int CIN  = 512;
constexpr int HH   = 56;
constexpr int WW   = 56;
constexpr int HW   = HH * WW;           // 3136
constexpr int COUT = 256;
constexpr int PP   = 28;
constexpr int PIX  = PP * PP;           // 784
constexpr int M_TOTAL = 64 * PIX;       // 50176
constexpr int MT   = 64;
constexpr int BK   = 32;
constexpr int NCH  = CIN / BK;          // 16

// A fp16 tile: row = 64B data + 16B pad = 80B (conflict-free ldmatrix).
constexpr int ARSB    = 80;
constexpr int A_BYTES = MT * ARSB;      // 5120 per stage
constexpr int A_OFF   = 4096;           // after scale/shift tables
// raw x ring: per pixel-pair: 32ch x (32B + 16B quad-shift pad) = 1152B
constexpr int PPSTRIDE  = 1152;
constexpr int RAW_STAGE = 32 * PPSTRIDE;          // 36864
constexpr int RAW_OFF   = A_OFF + 2 * A_BYTES;    // 14336
constexpr int SM_TOTAL  = RAW_OFF + 2 * RAW_STAGE; // 88064

// Prepacked B frags (fp16): [kc 32][nb 32][lane 32] -> uint2 {b0,b1}
constexpr int BUNITS = 32 * 32 * 32;
__device__ __align__(16) uint2 g_Bfrag[BUNITS];

#define MMA_F16(C, A, B0, B1)                                                \
    asm volatile("mma.sync.aligned.m16n8k16.row.col.f32.f16.f16.f32 "        \
                 "{%0,%1,%2,%3}, {%4,%5,%6,%7}, {%8,%9}, {%0,%1,%2,%3};"     \
                 : "+f"((C)[0]), "+f"((C)[1]), "+f"((C)[2]), "+f"((C)[3])    \
                 : "r"((A)[0]), "r"((A)[1]), "r"((A)[2]), "r"((A)[3]),       \
                   "r"(B0), "r"(B1))

#define LDMX4(R, ADDR)                                                       \
    asm volatile("ldmatrix.sync.aligned.m8n8.x4.shared.b16 {%0,%1,%2,%3}, [%4];" \
                 : "=r"((R)[0]), "=r"((R)[1]), "=r"((R)[2]), "=r"((R)[3])    \
                 : "r"(ADDR))

#define CP16(dst, src)                                                       \
    asm volatile("cp.async.cg.shared.global [%0], [%1], 16;"                 \
                 :: "r"(dst), "l"(src) : "memory")
#define CP_COMMIT() asm volatile("cp.async.commit_group;" ::: "memory")
#define CP_WAIT(N)  asm volatile("cp.async.wait_group %0;" :: "n"(N) : "memory")

#define LDS128F(f, addr)                                                     \
    asm volatile("ld.shared.v4.f32 {%0,%1,%2,%3}, [%4];"                     \
                 : "=f"((f).x), "=f"((f).y), "=f"((f).z), "=f"((f).w)        \
                 : "r"(addr))

__device__ __forceinline__ uint32_t smem_u32(const void* p) {
    uint32_t a;
    asm("{ .reg .u64 t; cvta.to.shared.u64 t, %1; cvt.u32.u64 %0, t; }" : "=r"(a) : "l"(p));
    return a;
}
__device__ __forceinline__ uint32_t pack2_f16(float v0, float v1) {
    __half h0 = __float2half_rn(v0);
    __half h1 = __float2half_rn(v1);
    return (uint32_t)__half_as_ushort(h0) | ((uint32_t)__half_as_ushort(h1) << 16);
}
__device__ __forceinline__ void sts64(uint32_t addr, uint32_t a, uint32_t b) {
    asm volatile("st.shared.v2.b32 [%0], {%1,%2};" :: "r"(addr), "r"(a), "r"(b) : "memory");
}

// ---------------- kernel 1: prepack B (fp16, fragment-major) ----------------
__global__ void prepack_B(const float* __restrict__ conv_w)
{
    const int idx = blockIdx.x * 256 + threadIdx.x;
    if (idx >= BUNITS) return;
    const int lane = idx & 31;
    const int nb   = (idx >> 5) & 31;
    const int kc   = idx >> 10;
    const int n  = nb * 8 + (lane >> 2);
    const int k0 = kc * 16 + (lane & 3) * 2;
    const float* wr = conv_w + (size_t)n * CIN;
    g_Bfrag[idx] = make_uint2(pack2_f16(wr[k0],     wr[k0 + 1]),
                              pack2_f16(wr[k0 + 8], wr[k0 + 9]));
}

// ---------------- kernel 2: main ----------------
__global__ __launch_bounds__(256, 2)
void transition_hmma9_kernel(const float* __restrict__ x,
                             const float* __restrict__ bn_w,
                             const float* __restrict__ bn_b,
                             const float* __restrict__ bn_m,
                             const float* __restrict__ bn_v,
                             float* __restrict__ out)
{
    extern __shared__ __align__(16) uint32_t sm[];
    float* s_scale = reinterpret_cast<float*>(sm);
    float* s_shift = reinterpret_cast<float*>(sm) + 512;
    const uint32_t sbase = smem_u32(sm);

    const int tid  = threadIdx.x;
    const int wid  = tid >> 5;          // warp n-slot: cols wid*32..+32
    const int lane = tid & 31;

    for (int c = tid; c < CIN; c += 256) {
        float inv = rsqrtf(bn_v[c] + BN_EPS);
        float sc  = bn_w[c] * inv;
        s_scale[c] = sc;
        s_shift[c] = bn_b[c] - bn_m[c] * sc;
    }

    const int m0 = blockIdx.x * MT;

    // ---- copier mapping: channel cc, 4 pixel-pairs ppb..ppb+3, 2 rows ----
    const int cc  = tid >> 3;           // 0..31
    const int ppb = (tid & 7) * 4;      // pixel-pair base
    const float* gp[4];
    #pragma unroll
    for (int k = 0; k < 4; k++) {
        const int m  = m0 + 2 * (ppb + k);
        const int im = m / PIX;
        const int pr = m % PIX;
        gp[k] = x + (size_t)im * (CIN * HW)
                  + (size_t)(2 * (pr / PP)) * WW + 2 * (pr % PP)
                  + (size_t)cc * HW;
    }
    const uint32_t coff = (uint32_t)(cc * 32 + (cc >> 2) * 16);

    // ---- converter mapping: pixel-pair vpp, channel quad vaq ----
    const int vpp = tid >> 3;
    const int vaq = tid & 7;
    const uint32_t cvt_rb0 = sbase + RAW_OFF + (uint32_t)(vpp * PPSTRIDE + vaq * 144);
    const uint32_t cvt_st0 = sbase + A_OFF + (uint32_t)((2 * vpp) * ARSB + vaq * 8);

    // ---- consumer mapping ----
    float acc[4][4][4];
    #pragma unroll
    for (int mh = 0; mh < 4; mh++)
        #pragma unroll
        for (int nn = 0; nn < 4; nn++)
            #pragma unroll
            for (int e = 0; e < 4; e++) acc[mh][nn][e] = 0.0f;

    const uint32_t a_ldm = sbase + A_OFF + (uint32_t)((lane & 15) * ARSB + ((lane >> 4) << 4));
    const uint2* bbase = g_Bfrag + (size_t)(wid * 4) * 32 + lane;

    auto copy_chunk = [&](int i) {
        const uint32_t rb = sbase + RAW_OFF + (uint32_t)((i & 1) * RAW_STAGE)
                          + (uint32_t)(ppb * PPSTRIDE) + coff;
        const size_t ch = (size_t)(i * BK) * HW;
        #pragma unroll
        for (int k = 0; k < 4; k++) {
            const float* g = gp[k] + ch;
            CP16(rb + (uint32_t)(k * PPSTRIDE),      g);
            CP16(rb + (uint32_t)(k * PPSTRIDE) + 16, g + WW);
        }
    };

    auto convert = [&](int i) {
        const uint32_t rb = cvt_rb0 + (uint32_t)((i & 1) * RAW_STAGE);
        float vL[4], vR[4];
        #pragma unroll
        for (int e = 0; e < 4; e++) {
            float4 r0, r1;
            LDS128F(r0, rb + (uint32_t)(e * 32));
            LDS128F(r1, rb + (uint32_t)(e * 32) + 16);
            const int c = i * BK + vaq * 4 + e;
            const float sc = s_scale[c], sh = s_shift[c];
            vL[e] = 0.25f * (fmaxf(fmaf(r0.x, sc, sh), 0.0f)
                           + fmaxf(fmaf(r0.y, sc, sh), 0.0f)
                           + fmaxf(fmaf(r1.x, sc, sh), 0.0f)
                           + fmaxf(fmaf(r1.y, sc, sh), 0.0f));
            vR[e] = 0.25f * (fmaxf(fmaf(r0.z, sc, sh), 0.0f)
                           + fmaxf(fmaf(r0.w, sc, sh), 0.0f)
                           + fmaxf(fmaf(r1.z, sc, sh), 0.0f)
                           + fmaxf(fmaf(r1.w, sc, sh), 0.0f));
        }
        const uint32_t st = cvt_st0 + (uint32_t)((i & 1) * A_BYTES);
        sts64(st,        pack2_f16(vL[0], vL[1]), pack2_f16(vL[2], vL[3]));
        sts64(st + ARSB, pack2_f16(vR[0], vR[1]), pack2_f16(vR[2], vR[3]));
    };

    auto ldB = [&](int kc, uint2* dst) {
        const uint2* bp = bbase + (size_t)kc * (32 * 32);
        #pragma unroll
        for (int nn = 0; nn < 4; nn++) dst[nn] = __ldg(bp + nn * 32);
    };

    auto compute_ks = [&](int i, int ks, const uint2* bcur, uint2* bnxt, int kc_next) {
        const uint32_t aa = a_ldm + (uint32_t)((i & 1) * A_BYTES) + (uint32_t)(ks * 32);
        uint32_t ah[4][4];
        #pragma unroll
        for (int mh = 0; mh < 4; mh++)
            LDMX4(ah[mh], aa + (uint32_t)(mh * 16 * ARSB));
        ldB(kc_next, bnxt);   // in flight under the MMAs below
        #pragma unroll
        for (int nn = 0; nn < 4; nn++) {
            #pragma unroll
            for (int mh = 0; mh < 4; mh++)
                MMA_F16(acc[mh][nn], ah[mh], bcur[nn].x, bcur[nn].y);
        }
    };

    // ---------- prologue ----------
    uint2 bbuf0[4], bbuf1[4];
    copy_chunk(0); CP_COMMIT();
    copy_chunk(1); CP_COMMIT();
    ldB(0, bbuf0);
    CP_WAIT(1);
    __syncthreads();            // publishes chunk0 raw + BN tables
    convert(0);

    // ---------- main loop: 1 barrier per chunk ----------
    #pragma unroll 1
    for (int i = 0; i < NCH; i++) {
        if (i + 1 < NCH) CP_WAIT(0);     // raw[i+1] complete (only group in flight)
        __syncthreads();                  // publish raw[i+1] + A[i&1]
        if (i + 2 < NCH) { copy_chunk(i + 2); CP_COMMIT(); }
        const int kc1 = i * 2 + 1;
        const int kc2 = (i + 1 < NCH) ? (i * 2 + 2) : 31;
        compute_ks(i, 0, bbuf0, bbuf1, kc1);
        if (i + 1 < NCH) convert(i + 1);  // hides under ks1 MMAs
        compute_ks(i, 1, bbuf1, bbuf0, kc2);
    }

    // ---------- epilogue: warp covers 64m x 32n ----------
    const int fr = lane >> 2;
    const int q2 = (lane & 3) * 2;
    #pragma unroll
    for (int mh = 0; mh < 4; mh++) {
        #pragma unroll
        for (int half = 0; half < 2; half++) {
            const int m  = m0 + mh * 16 + fr + half * 8;
            const int im = m / PIX;
            const int px = m % PIX;
            float* ob = out + (size_t)im * (COUT * PIX) + px;
            #pragma unroll
            for (int nn = 0; nn < 4; nn++) {
                const int n = wid * 32 + nn * 8 + q2;
                ob[(size_t)n * PIX]       = acc[mh][nn][half * 2];
                ob[(size_t)(n + 1) * PIX] = acc[mh][nn][half * 2 + 1];
            }
        }
    }
}

extern "C" void kernel_launch(void* const* d_in, const int* in_sizes, int n_in,
                              void* d_out, int out_size)
{
    const float* x      = (const float*)d_in[0];
    const float* bn_w   = (const float*)d_in[1];
    const float* bn_b   = (const float*)d_in[2];
    const float* bn_m   = (const float*)d_in[3];
    const float* bn_v   = (const float*)d_in[4];
    const float* conv_w = (const float*)d_in[5];
    float* out = (float*)d_out;

    prepack_B<<<(BUNITS + 255) / 256, 256>>>(conv_w);

    cudaFuncSetAttribute(transition_hmma9_kernel,
                         cudaFuncAttributeMaxDynamicSharedMemorySize, SM_TOTAL);
    transition_hmma9_kernel<<<M_TOTAL / MT, 256, SM_TOTAL>>>(
        x, bn_w, bn_b, bn_m, bn_v, out);
}

// round 13
// speedup vs baseline: 1.0042x; 1.0042x over previous
#include <cuda_runtime.h>
#include <cuda_fp16.h>
#include <cstdint>

// TransitionLayer: BN(eval)+ReLU+1x1conv(512->256)+avgpool2x2, NCHW fp32.
// pool(conv(act)) == conv(pool(act)) -> GEMM M=50176, K=512, N=256.
// R13: R12 architecture with the pipeline bug fixed. cp.async raw-x ring,
//      distance-1-chunk prefetch (wait_group(0) drains ONLY chunk i+1 because
//      chunk i+2 is committed after the wait), ONE barrier per chunk.
//      Consumer = R11 (64m x 32n warp tile, B reg pipeline, 1-term fp16).

#define BN_EPS 1e-5f

constexpr int CIN  = 512;
constexpr int HH   = 56;
constexpr int WW   = 56;
constexpr int HW   = HH * WW;           // 3136
constexpr int COUT = 256;
constexpr int PP   = 28;
constexpr int PIX  = PP * PP;           // 784
constexpr int M_TOTAL = 64 * PIX;       // 50176
constexpr int MT   = 64;
constexpr int BK   = 32;
constexpr int NCH  = CIN / BK;          // 16

// A fp16 tile: row = 64B data + 16B pad = 80B (conflict-free ldmatrix).
constexpr int ARSB    = 80;
constexpr int A_BYTES = MT * ARSB;      // 5120 per stage
constexpr int A_OFF   = 4096;
// raw x ring: per pixel-pair: 32ch x (32B + 16B quad-shift pad) = 1152B
constexpr int PPSTRIDE  = 1152;
constexpr int RAW_STAGE = 32 * PPSTRIDE;          // 36864
constexpr int RAW_OFF   = A_OFF + 2 * A_BYTES;    // 14336
constexpr int SM_TOTAL  = RAW_OFF + 2 * RAW_STAGE; // 88064

// Prepacked B frags (fp16): [kc 32][nb 32][lane 32] -> uint2 {b0,b1}
constexpr int BUNITS = 32 * 32 * 32;
__device__ __align__(16) uint2 g_Bfrag[BUNITS];

#define MMA_F16(C, A, B0, B1)                                                \
    asm volatile("mma.sync.aligned.m16n8k16.row.col.f32.f16.f16.f32 "        \
                 "{%0,%1,%2,%3}, {%4,%5,%6,%7}, {%8,%9}, {%0,%1,%2,%3};"     \
                 : "+f"((C)[0]), "+f"((C)[1]), "+f"((C)[2]), "+f"((C)[3])    \
                 : "r"((A)[0]), "r"((A)[1]), "r"((A)[2]), "r"((A)[3]),       \
                   "r"(B0), "r"(B1))

#define LDMX4(R, ADDR)                                                       \
    asm volatile("ldmatrix.sync.aligned.m8n8.x4.shared.b16 {%0,%1,%2,%3}, [%4];" \
                 : "=r"((R)[0]), "=r"((R)[1]), "=r"((R)[2]), "=r"((R)[3])    \
                 : "r"(ADDR))

#define CP16(dst, src)                                                       \
    asm volatile("cp.async.cg.shared.global [%0], [%1], 16;"                 \
                 :: "r"(dst), "l"(src) : "memory")
#define CP_COMMIT() asm volatile("cp.async.commit_group;" ::: "memory")
#define CP_WAIT(N)  asm volatile("cp.async.wait_group %0;" :: "n"(N) : "memory")

#define LDS128F(f, addr)                                                     \
    asm volatile("ld.shared.v4.f32 {%0,%1,%2,%3}, [%4];"                     \
                 : "=f"((f).x), "=f"((f).y), "=f"((f).z), "=f"((f).w)        \
                 : "r"(addr))

__device__ __forceinline__ uint32_t smem_u32(const void* p) {
    uint32_t a;
    asm("{ .reg .u64 t; cvta.to.shared.u64 t, %1; cvt.u32.u64 %0, t; }" : "=r"(a) : "l"(p));
    return a;
}
__device__ __forceinline__ uint32_t pack2_f16(float v0, float v1) {
    __half h0 = __float2half_rn(v0);
    __half h1 = __float2half_rn(v1);
    return (uint32_t)__half_as_ushort(h0) | ((uint32_t)__half_as_ushort(h1) << 16);
}
__device__ __forceinline__ void sts64(uint32_t addr, uint32_t a, uint32_t b) {
    asm volatile("st.shared.v2.b32 [%0], {%1,%2};" :: "r"(addr), "r"(a), "r"(b) : "memory");
}

// ---------------- kernel 1: prepack B (fp16, fragment-major) ----------------
__global__ void prepack_B(const float* __restrict__ conv_w)
{
    const int idx = blockIdx.x * 256 + threadIdx.x;
    if (idx >= BUNITS) return;
    const int lane = idx & 31;
    const int nb   = (idx >> 5) & 31;
    const int kc   = idx >> 10;
    const int n  = nb * 8 + (lane >> 2);
    const int k0 = kc * 16 + (lane & 3) * 2;
    const float* wr = conv_w + (size_t)n * CIN;
    g_Bfrag[idx] = make_uint2(pack2_f16(wr[k0],     wr[k0 + 1]),
                              pack2_f16(wr[k0 + 8], wr[k0 + 9]));
}

// ---------------- kernel 2: main ----------------
__global__ __launch_bounds__(256, 2)
void transition_hmma10_kernel(const float* __restrict__ x,
                              const float* __restrict__ bn_w,
                              const float* __restrict__ bn_b,
                              const float* __restrict__ bn_m,
                              const float* __restrict__ bn_v,
                              float* __restrict__ out)
{
    extern __shared__ __align__(16) uint32_t sm[];
    float* s_scale = reinterpret_cast<float*>(sm);
    float* s_shift = reinterpret_cast<float*>(sm) + 512;
    const uint32_t sbase = smem_u32(sm);

    const int tid  = threadIdx.x;
    const int wid  = tid >> 5;          // warp n-slot: cols wid*32..+32
    const int lane = tid & 31;

    for (int c = tid; c < CIN; c += 256) {
        float inv = rsqrtf(bn_v[c] + BN_EPS);
        float sc  = bn_w[c] * inv;
        s_scale[c] = sc;
        s_shift[c] = bn_b[c] - bn_m[c] * sc;
    }

    const int m0 = blockIdx.x * MT;

    // ---- copier mapping: channel cc, 4 pixel-pairs ppb..ppb+3, 2 rows ----
    const int cc  = tid >> 3;           // 0..31
    const int ppb = (tid & 7) * 4;      // pixel-pair base
    const float* gp[4];
    #pragma unroll
    for (int k = 0; k < 4; k++) {
        const int m  = m0 + 2 * (ppb + k);
        const int im = m / PIX;
        const int pr = m % PIX;
        gp[k] = x + (size_t)im * (CIN * HW)
                  + (size_t)(2 * (pr / PP)) * WW + 2 * (pr % PP)
                  + (size_t)cc * HW;
    }
    const uint32_t coff = (uint32_t)(cc * 32 + (cc >> 2) * 16);

    // ---- converter mapping: pixel-pair vpp, channel quad vaq ----
    const int vpp = tid >> 3;
    const int vaq = tid & 7;
    const uint32_t cvt_rb0 = sbase + RAW_OFF + (uint32_t)(vpp * PPSTRIDE + vaq * 144);
    const uint32_t cvt_st0 = sbase + A_OFF + (uint32_t)((2 * vpp) * ARSB + vaq * 8);

    // ---- consumer state ----
    float acc[4][4][4];
    #pragma unroll
    for (int mh = 0; mh < 4; mh++)
        #pragma unroll
        for (int nn = 0; nn < 4; nn++)
            #pragma unroll
            for (int e = 0; e < 4; e++) acc[mh][nn][e] = 0.0f;

    const uint32_t a_ldm = sbase + A_OFF + (uint32_t)((lane & 15) * ARSB + ((lane >> 4) << 4));
    const uint2* bbase = g_Bfrag + (size_t)(wid * 4) * 32 + lane;

    auto copy_chunk = [&](int i) {
        const uint32_t rb = sbase + RAW_OFF + (uint32_t)((i & 1) * RAW_STAGE)
                          + (uint32_t)(ppb * PPSTRIDE) + coff;
        const size_t ch = (size_t)(i * BK) * HW;
        #pragma unroll
        for (int k = 0; k < 4; k++) {
            const float* g = gp[k] + ch;
            CP16(rb + (uint32_t)(k * PPSTRIDE),      g);
            CP16(rb + (uint32_t)(k * PPSTRIDE) + 16, g + WW);
        }
    };

    auto convert = [&](int i) {
        const uint32_t rb = cvt_rb0 + (uint32_t)((i & 1) * RAW_STAGE);
        float vL[4], vR[4];
        #pragma unroll
        for (int e = 0; e < 4; e++) {
            float4 r0, r1;
            LDS128F(r0, rb + (uint32_t)(e * 32));
            LDS128F(r1, rb + (uint32_t)(e * 32) + 16);
            const int c = i * BK + vaq * 4 + e;
            const float sc = s_scale[c], sh = s_shift[c];
            vL[e] = 0.25f * (fmaxf(fmaf(r0.x, sc, sh), 0.0f)
                           + fmaxf(fmaf(r0.y, sc, sh), 0.0f)
                           + fmaxf(fmaf(r1.x, sc, sh), 0.0f)
                           + fmaxf(fmaf(r1.y, sc, sh), 0.0f));
            vR[e] = 0.25f * (fmaxf(fmaf(r0.z, sc, sh), 0.0f)
                           + fmaxf(fmaf(r0.w, sc, sh), 0.0f)
                           + fmaxf(fmaf(r1.z, sc, sh), 0.0f)
                           + fmaxf(fmaf(r1.w, sc, sh), 0.0f));
        }
        const uint32_t st = cvt_st0 + (uint32_t)((i & 1) * A_BYTES);
        sts64(st,        pack2_f16(vL[0], vL[1]), pack2_f16(vL[2], vL[3]));
        sts64(st + ARSB, pack2_f16(vR[0], vR[1]), pack2_f16(vR[2], vR[3]));
    };

    auto ldB = [&](int kc, uint2* dst) {
        const uint2* bp = bbase + (size_t)kc * (32 * 32);
        #pragma unroll
        for (int nn = 0; nn < 4; nn++) dst[nn] = __ldg(bp + nn * 32);
    };

    auto compute_ks = [&](int i, int ks, const uint2* bcur, uint2* bnxt, int kc_next) {
        const uint32_t aa = a_ldm + (uint32_t)((i & 1) * A_BYTES) + (uint32_t)(ks * 32);
        uint32_t ah[4][4];
        #pragma unroll
        for (int mh = 0; mh < 4; mh++)
            LDMX4(ah[mh], aa + (uint32_t)(mh * 16 * ARSB));
        ldB(kc_next, bnxt);   // in flight under the MMAs below
        #pragma unroll
        for (int nn = 0; nn < 4; nn++) {
            #pragma unroll
            for (int mh = 0; mh < 4; mh++)
                MMA_F16(acc[mh][nn], ah[mh], bcur[nn].x, bcur[nn].y);
        }
    };

    // ---------- prologue ----------
    uint2 bbuf0[4], bbuf1[4];
    copy_chunk(0); CP_COMMIT();
    copy_chunk(1); CP_COMMIT();
    ldB(0, bbuf0);
    CP_WAIT(1);                 // chunk0 raw done (chunk1 still flying)
    __syncthreads();            // publish raw0 + BN tables
    convert(0);                 // A[stage 0]

    // ---------- main loop: ONE barrier per chunk ----------
    #pragma unroll 1
    for (int i = 0; i < NCH; i++) {
        CP_WAIT(0);             // pending = {i+1} only -> drains exactly chunk i+1,
                                // which has been flying for a full chunk
        __syncthreads();        // publish raw[i+1] + A[i&1]; fence stage reuse
        if (i + 2 < NCH) { copy_chunk(i + 2); CP_COMMIT(); }  // raw stage i&1: safe
        const int kc1 = i * 2 + 1;
        const int kc2 = (i + 1 < NCH) ? (i * 2 + 2) : 31;
        compute_ks(i, 0, bbuf0, bbuf1, kc1);
        if (i + 1 < NCH) convert(i + 1);   // LDS-based, hides under ks1 MMAs
        compute_ks(i, 1, bbuf1, bbuf0, kc2);
    }

    // ---------- epilogue: warp covers 64m x 32n ----------
    const int fr = lane >> 2;
    const int q2 = (lane & 3) * 2;
    #pragma unroll
    for (int mh = 0; mh < 4; mh++) {
        #pragma unroll
        for (int half = 0; half < 2; half++) {
            const int m  = m0 + mh * 16 + fr + half * 8;
            const int im = m / PIX;
            const int px = m % PIX;
            float* ob = out + (size_t)im * (COUT * PIX) + px;
            #pragma unroll
            for (int nn = 0; nn < 4; nn++) {
                const int n = wid * 32 + nn * 8 + q2;
                ob[(size_t)n * PIX]       = acc[mh][nn][half * 2];
                ob[(size_t)(n + 1) * PIX] = acc[mh][nn][half * 2 + 1];
            }
        }
    }
}

extern "C" void kernel_launch(void* const* d_in, const int* in_sizes, int n_in,
                              void* d_out, int out_size)
{
    const float* x      = (const float*)d_in[0];
    const float* bn_w   = (const float*)d_in[1];
    const float* bn_b   = (const float*)d_in[2];
    const float* bn_m   = (const float*)d_in[3];
    const float* bn_v   = (const float*)d_in[4];
    const float* conv_w = (const float*)d_in[5];
    float* out = (float*)d_out;

    prepack_B<<<(BUNITS + 255) / 256, 256>>>(conv_w);

    cudaFuncSetAttribute(transition_hmma10_kernel,
                         cudaFuncAttributeMaxDynamicSharedMemorySize, SM_TOTAL);
    transition_hmma10_kernel<<<M_TOTAL / MT, 256, SM_TOTAL>>>(
        x, bn_w, bn_b, bn_m, bn_v, out);
}

// round 14
// speedup vs baseline: 1.1768x; 1.1719x over previous
#include <cuda_runtime.h>
#include <cuda_fp16.h>
#include <cstdint>

// TransitionLayer: BN(eval)+ReLU+1x1conv(512->256)+avgpool2x2, NCHW fp32.
// pool(conv(act)) == conv(pool(act)) -> GEMM M=50176, K=512, N=256.
// R14: R13 with the copier COALESCING fixed: thread (cc, tid&7) copies pairs
//      {(tid&7)+8k}, so each warp cp.async instruction covers 128B contiguous
//      per channel (full 32B sectors). Pipeline/converter/consumer unchanged:
//      cp.async raw ring (distance 1 chunk), 1 barrier/chunk, 64m x 32n warp
//      tile, B reg pipeline, single-term fp16 HMMA.

#define BN_EPS 1e-5f

constexpr int CIN  = 512;
constexpr int HH   = 56;
constexpr int WW   = 56;
constexpr int HW   = HH * WW;           // 3136
constexpr int COUT = 256;
constexpr int PP   = 28;
constexpr int PIX  = PP * PP;           // 784
constexpr int M_TOTAL = 64 * PIX;       // 50176
constexpr int MT   = 64;
constexpr int BK   = 32;
constexpr int NCH  = CIN / BK;          // 16

// A fp16 tile: row = 64B data + 16B pad = 80B (conflict-free ldmatrix).
constexpr int ARSB    = 80;
constexpr int A_BYTES = MT * ARSB;      // 5120 per stage
constexpr int A_OFF   = 4096;
// raw x ring: per pixel-pair: 32ch x (32B + 16B quad-shift pad) = 1152B
constexpr int PPSTRIDE  = 1152;
constexpr int RAW_STAGE = 32 * PPSTRIDE;          // 36864
constexpr int RAW_OFF   = A_OFF + 2 * A_BYTES;    // 14336
constexpr int SM_TOTAL  = RAW_OFF + 2 * RAW_STAGE; // 88064

// Prepacked B frags (fp16): [kc 32][nb 32][lane 32] -> uint2 {b0,b1}
constexpr int BUNITS = 32 * 32 * 32;
__device__ __align__(16) uint2 g_Bfrag[BUNITS];

#define MMA_F16(C, A, B0, B1)                                                \
    asm volatile("mma.sync.aligned.m16n8k16.row.col.f32.f16.f16.f32 "        \
                 "{%0,%1,%2,%3}, {%4,%5,%6,%7}, {%8,%9}, {%0,%1,%2,%3};"     \
                 : "+f"((C)[0]), "+f"((C)[1]), "+f"((C)[2]), "+f"((C)[3])    \
                 : "r"((A)[0]), "r"((A)[1]), "r"((A)[2]), "r"((A)[3]),       \
                   "r"(B0), "r"(B1))

#define LDMX4(R, ADDR)                                                       \
    asm volatile("ldmatrix.sync.aligned.m8n8.x4.shared.b16 {%0,%1,%2,%3}, [%4];" \
                 : "=r"((R)[0]), "=r"((R)[1]), "=r"((R)[2]), "=r"((R)[3])    \
                 : "r"(ADDR))

#define CP16(dst, src)                                                       \
    asm volatile("cp.async.cg.shared.global [%0], [%1], 16;"                 \
                 :: "r"(dst), "l"(src) : "memory")
#define CP_COMMIT() asm volatile("cp.async.commit_group;" ::: "memory")
#define CP_WAIT(N)  asm volatile("cp.async.wait_group %0;" :: "n"(N) : "memory")

#define LDS128F(f, addr)                                                     \
    asm volatile("ld.shared.v4.f32 {%0,%1,%2,%3}, [%4];"                     \
                 : "=f"((f).x), "=f"((f).y), "=f"((f).z), "=f"((f).w)        \
                 : "r"(addr))

__device__ __forceinline__ uint32_t smem_u32(const void* p) {
    uint32_t a;
    asm("{ .reg .u64 t; cvta.to.shared.u64 t, %1; cvt.u32.u64 %0, t; }" : "=r"(a) : "l"(p));
    return a;
}
__device__ __forceinline__ uint32_t pack2_f16(float v0, float v1) {
    __half h0 = __float2half_rn(v0);
    __half h1 = __float2half_rn(v1);
    return (uint32_t)__half_as_ushort(h0) | ((uint32_t)__half_as_ushort(h1) << 16);
}
__device__ __forceinline__ void sts64(uint32_t addr, uint32_t a, uint32_t b) {
    asm volatile("st.shared.v2.b32 [%0], {%1,%2};" :: "r"(addr), "r"(a), "r"(b) : "memory");
}

// ---------------- kernel 1: prepack B (fp16, fragment-major) ----------------
__global__ void prepack_B(const float* __restrict__ conv_w)
{
    const int idx = blockIdx.x * 256 + threadIdx.x;
    if (idx >= BUNITS) return;
    const int lane = idx & 31;
    const int nb   = (idx >> 5) & 31;
    const int kc   = idx >> 10;
    const int n  = nb * 8 + (lane >> 2);
    const int k0 = kc * 16 + (lane & 3) * 2;
    const float* wr = conv_w + (size_t)n * CIN;
    g_Bfrag[idx] = make_uint2(pack2_f16(wr[k0],     wr[k0 + 1]),
                              pack2_f16(wr[k0 + 8], wr[k0 + 9]));
}

// ---------------- kernel 2: main ----------------
__global__ __launch_bounds__(256, 2)
void transition_hmma11_kernel(const float* __restrict__ x,
                              const float* __restrict__ bn_w,
                              const float* __restrict__ bn_b,
                              const float* __restrict__ bn_m,
                              const float* __restrict__ bn_v,
                              float* __restrict__ out)
{
    extern __shared__ __align__(16) uint32_t sm[];
    float* s_scale = reinterpret_cast<float*>(sm);
    float* s_shift = reinterpret_cast<float*>(sm) + 512;
    const uint32_t sbase = smem_u32(sm);

    const int tid  = threadIdx.x;
    const int wid  = tid >> 5;          // warp n-slot: cols wid*32..+32
    const int lane = tid & 31;

    for (int c = tid; c < CIN; c += 256) {
        float inv = rsqrtf(bn_v[c] + BN_EPS);
        float sc  = bn_w[c] * inv;
        s_scale[c] = sc;
        s_shift[c] = bn_b[c] - bn_m[c] * sc;
    }

    const int m0 = blockIdx.x * MT;

    // ---- copier mapping (COALESCED): channel cc; pairs p = pl + 8k, k=0..3
    //      -> per warp cp.async instr, lanes pl=0..7 cover 128B contiguous / cc.
    const int cc = tid >> 3;            // 0..31
    const int pl = tid & 7;             // pair lane
    const float* gp[4];
    #pragma unroll
    for (int k = 0; k < 4; k++) {
        const int p  = pl + 8 * k;
        const int m  = m0 + 2 * p;
        const int im = m / PIX;
        const int pr = m % PIX;
        gp[k] = x + (size_t)im * (CIN * HW)
                  + (size_t)(2 * (pr / PP)) * WW + 2 * (pr % PP)
                  + (size_t)cc * HW;
    }
    const uint32_t coff = (uint32_t)(cc * 32 + (cc >> 2) * 16);

    // ---- converter mapping: pixel-pair vpp, channel quad vaq ----
    const int vpp = tid >> 3;
    const int vaq = tid & 7;
    const uint32_t cvt_rb0 = sbase + RAW_OFF + (uint32_t)(vpp * PPSTRIDE + vaq * 144);
    const uint32_t cvt_st0 = sbase + A_OFF + (uint32_t)((2 * vpp) * ARSB + vaq * 8);

    // ---- consumer state ----
    float acc[4][4][4];
    #pragma unroll
    for (int mh = 0; mh < 4; mh++)
        #pragma unroll
        for (int nn = 0; nn < 4; nn++)
            #pragma unroll
            for (int e = 0; e < 4; e++) acc[mh][nn][e] = 0.0f;

    const uint32_t a_ldm = sbase + A_OFF + (uint32_t)((lane & 15) * ARSB + ((lane >> 4) << 4));
    const uint2* bbase = g_Bfrag + (size_t)(wid * 4) * 32 + lane;

    auto copy_chunk = [&](int i) {
        const uint32_t rb = sbase + RAW_OFF + (uint32_t)((i & 1) * RAW_STAGE) + coff;
        const size_t ch = (size_t)(i * BK) * HW;
        #pragma unroll
        for (int k = 0; k < 4; k++) {
            const float* g = gp[k] + ch;
            const uint32_t d = rb + (uint32_t)((pl + 8 * k) * PPSTRIDE);
            CP16(d,      g);
            CP16(d + 16, g + WW);
        }
    };

    auto convert = [&](int i) {
        const uint32_t rb = cvt_rb0 + (uint32_t)((i & 1) * RAW_STAGE);
        float vL[4], vR[4];
        #pragma unroll
        for (int e = 0; e < 4; e++) {
            float4 r0, r1;
            LDS128F(r0, rb + (uint32_t)(e * 32));
            LDS128F(r1, rb + (uint32_t)(e * 32) + 16);
            const int c = i * BK + vaq * 4 + e;
            const float sc = s_scale[c], sh = s_shift[c];
            vL[e] = 0.25f * (fmaxf(fmaf(r0.x, sc, sh), 0.0f)
                           + fmaxf(fmaf(r0.y, sc, sh), 0.0f)
                           + fmaxf(fmaf(r1.x, sc, sh), 0.0f)
                           + fmaxf(fmaf(r1.y, sc, sh), 0.0f));
            vR[e] = 0.25f * (fmaxf(fmaf(r0.z, sc, sh), 0.0f)
                           + fmaxf(fmaf(r0.w, sc, sh), 0.0f)
                           + fmaxf(fmaf(r1.z, sc, sh), 0.0f)
                           + fmaxf(fmaf(r1.w, sc, sh), 0.0f));
        }
        const uint32_t st = cvt_st0 + (uint32_t)((i & 1) * A_BYTES);
        sts64(st,        pack2_f16(vL[0], vL[1]), pack2_f16(vL[2], vL[3]));
        sts64(st + ARSB, pack2_f16(vR[0], vR[1]), pack2_f16(vR[2], vR[3]));
    };

    auto ldB = [&](int kc, uint2* dst) {
        const uint2* bp = bbase + (size_t)kc * (32 * 32);
        #pragma unroll
        for (int nn = 0; nn < 4; nn++) dst[nn] = __ldg(bp + nn * 32);
    };

    auto compute_ks = [&](int i, int ks, const uint2* bcur, uint2* bnxt, int kc_next) {
        const uint32_t aa = a_ldm + (uint32_t)((i & 1) * A_BYTES) + (uint32_t)(ks * 32);
        uint32_t ah[4][4];
        #pragma unroll
        for (int mh = 0; mh < 4; mh++)
            LDMX4(ah[mh], aa + (uint32_t)(mh * 16 * ARSB));
        ldB(kc_next, bnxt);   // in flight under the MMAs below
        #pragma unroll
        for (int nn = 0; nn < 4; nn++) {
            #pragma unroll
            for (int mh = 0; mh < 4; mh++)
                MMA_F16(acc[mh][nn], ah[mh], bcur[nn].x, bcur[nn].y);
        }
    };

    // ---------- prologue ----------
    uint2 bbuf0[4], bbuf1[4];
    copy_chunk(0); CP_COMMIT();
    copy_chunk(1); CP_COMMIT();
    ldB(0, bbuf0);
    CP_WAIT(1);                 // chunk0 raw done (chunk1 still flying)
    __syncthreads();            // publish raw0 + BN tables
    convert(0);                 // A[stage 0]

    // ---------- main loop: ONE barrier per chunk ----------
    #pragma unroll 1
    for (int i = 0; i < NCH; i++) {
        CP_WAIT(0);             // drains exactly chunk i+1 (one full chunk in flight)
        __syncthreads();        // publish raw[i+1] + A[i&1]; fence stage reuse
        if (i + 2 < NCH) { copy_chunk(i + 2); CP_COMMIT(); }
        const int kc1 = i * 2 + 1;
        const int kc2 = (i + 1 < NCH) ? (i * 2 + 2) : 31;
        compute_ks(i, 0, bbuf0, bbuf1, kc1);
        if (i + 1 < NCH) convert(i + 1);   // hides under ks1 MMAs
        compute_ks(i, 1, bbuf1, bbuf0, kc2);
    }

    // ---------- epilogue: warp covers 64m x 32n ----------
    const int fr = lane >> 2;
    const int q2 = (lane & 3) * 2;
    #pragma unroll
    for (int mh = 0; mh < 4; mh++) {
        #pragma unroll
        for (int half = 0; half < 2; half++) {
            const int m  = m0 + mh * 16 + fr + half * 8;
            const int im = m / PIX;
            const int px = m % PIX;
            float* ob = out + (size_t)im * (COUT * PIX) + px;
            #pragma unroll
            for (int nn = 0; nn < 4; nn++) {
                const int n = wid * 32 + nn * 8 + q2;
                ob[(size_t)n * PIX]       = acc[mh][nn][half * 2];
                ob[(size_t)(n + 1) * PIX] = acc[mh][nn][half * 2 + 1];
            }
        }
    }
}

extern "C" void kernel_launch(void* const* d_in, const int* in_sizes, int n_in,
                              void* d_out, int out_size)
{
    const float* x      = (const float*)d_in[0];
    const float* bn_w   = (const float*)d_in[1];
    const float* bn_b   = (const float*)d_in[2];
    const float* bn_m   = (const float*)d_in[3];
    const float* bn_v   = (const float*)d_in[4];
    const float* conv_w = (const float*)d_in[5];
    float* out = (float*)d_out;

    prepack_B<<<(BUNITS + 255) / 256, 256>>>(conv_w);

    cudaFuncSetAttribute(transition_hmma11_kernel,
                         cudaFuncAttributeMaxDynamicSharedMemorySize, SM_TOTAL);
    transition_hmma11_kernel<<<M_TOTAL / MT, 256, SM_TOTAL>>>(
        x, bn_w, bn_b, bn_m, bn_v, out);
}

// round 15
// speedup vs baseline: 1.3979x; 1.1879x over previous
#include <cuda_runtime.h>
#include <cuda_fp16.h>
#include <cstdint>

// TransitionLayer: BN(eval)+ReLU+1x1conv(512->256)+avgpool2x2, NCHW fp32.
// pool(conv(act)) == conv(pool(act)) -> GEMM M=50176, K=512, N=256.
// R15: R11 frame (best: direct-LDG producer, 64m x 32n warp tile, B reg
//      pipeline, single-term fp16 HMMA) + prefetch.global.L2 of chunk i+2's
//      x data: fire-and-forget DRAM MLP (no regs, no smem), and the blocking
//      chunk-(i+1) LDGs become L2 hits (~250cyc) instead of DRAM (577cyc).

#define BN_EPS 1e-5f

constexpr int CIN  = 512;
constexpr int HH   = 56;
constexpr int WW   = 56;
constexpr int HW   = HH * WW;           // 3136
constexpr int COUT = 256;
constexpr int PP   = 28;
constexpr int PIX  = PP * PP;           // 784
constexpr int M_TOTAL = 64 * PIX;       // 50176
constexpr int MT   = 64;
constexpr int BK   = 32;
constexpr int NCH  = CIN / BK;          // 16

// A smem: fp16, row = 64B data + 16B pad = 80B stride (conflict-free ldmatrix).
constexpr int ARSB    = 80;
constexpr int A_BYTES = MT * ARSB;           // 5120 per stage
constexpr int TILE_OFF = 4096;
constexpr int SM_TOTAL = TILE_OFF + 2 * A_BYTES;   // 14336

// Prepacked B frags (fp16): [kc 32][nb 32][lane 32] -> uint2 {b0,b1}
constexpr int BUNITS = 32 * 32 * 32;
__device__ __align__(16) uint2 g_Bfrag[BUNITS];

#define MMA_F16(C, A, B0, B1)                                                \
    asm volatile("mma.sync.aligned.m16n8k16.row.col.f32.f16.f16.f32 "        \
                 "{%0,%1,%2,%3}, {%4,%5,%6,%7}, {%8,%9}, {%0,%1,%2,%3};"     \
                 : "+f"((C)[0]), "+f"((C)[1]), "+f"((C)[2]), "+f"((C)[3])    \
                 : "r"((A)[0]), "r"((A)[1]), "r"((A)[2]), "r"((A)[3]),       \
                   "r"(B0), "r"(B1))

#define LDMX4(R, ADDR)                                                       \
    asm volatile("ldmatrix.sync.aligned.m8n8.x4.shared.b16 {%0,%1,%2,%3}, [%4];" \
                 : "=r"((R)[0]), "=r"((R)[1]), "=r"((R)[2]), "=r"((R)[3])    \
                 : "r"(ADDR))

#define PF_L2(p) asm volatile("prefetch.global.L2 [%0];" :: "l"(p))

__device__ __forceinline__ uint32_t smem_u32(const void* p) {
    uint32_t a;
    asm("{ .reg .u64 t; cvta.to.shared.u64 t, %1; cvt.u32.u64 %0, t; }" : "=r"(a) : "l"(p));
    return a;
}
__device__ __forceinline__ uint32_t pack2_f16(float v0, float v1) {
    __half h0 = __float2half_rn(v0);
    __half h1 = __float2half_rn(v1);
    return (uint32_t)__half_as_ushort(h0) | ((uint32_t)__half_as_ushort(h1) << 16);
}
__device__ __forceinline__ void sts64(uint32_t addr, uint32_t a, uint32_t b) {
    asm volatile("st.shared.v2.b32 [%0], {%1,%2};" :: "r"(addr), "r"(a), "r"(b) : "memory");
}

// ---------------- kernel 1: prepack B (fp16, fragment-major) ----------------
__global__ void prepack_B(const float* __restrict__ conv_w)
{
    const int idx = blockIdx.x * 256 + threadIdx.x;
    if (idx >= BUNITS) return;
    const int lane = idx & 31;
    const int nb   = (idx >> 5) & 31;
    const int kc   = idx >> 10;
    const int n  = nb * 8 + (lane >> 2);
    const int k0 = kc * 16 + (lane & 3) * 2;
    const float* wr = conv_w + (size_t)n * CIN;
    g_Bfrag[idx] = make_uint2(pack2_f16(wr[k0],     wr[k0 + 1]),
                              pack2_f16(wr[k0 + 8], wr[k0 + 9]));
}

// ---------------- kernel 2: main ----------------
__global__ __launch_bounds__(256, 2)
void transition_hmma12_kernel(const float* __restrict__ x,
                              const float* __restrict__ bn_w,
                              const float* __restrict__ bn_b,
                              const float* __restrict__ bn_m,
                              const float* __restrict__ bn_v,
                              float* __restrict__ out)
{
    extern __shared__ __align__(16) uint32_t sm[];
    float* s_scale = reinterpret_cast<float*>(sm);
    float* s_shift = reinterpret_cast<float*>(sm) + 512;
    const uint32_t sbase = smem_u32(sm);

    const int tid  = threadIdx.x;
    const int wid  = tid >> 5;          // warp n-slot: cols wid*32..+32
    const int lane = tid & 31;

    for (int c = tid; c < CIN; c += 256) {
        float inv = rsqrtf(bn_v[c] + BN_EPS);
        float sc  = bn_w[c] * inv;
        s_scale[c] = sc;
        s_shift[c] = bn_b[c] - bn_m[c] * sc;
    }

    const int m0 = blockIdx.x * MT;

    // producer: pxl row 0..63, aq covers channels aq*8 (2 waves of 4)
    const int pxl = tid >> 2;
    const int aq  = tid & 3;
    const int mg  = m0 + pxl;
    const int img = mg / PIX;
    const int pr  = mg % PIX;
    const float* xb = x + (size_t)img * (CIN * HW)
                        + (size_t)(2 * (pr / PP)) * WW + 2 * (pr % PP);

    float acc[4][4][4];
    #pragma unroll
    for (int mh = 0; mh < 4; mh++)
        #pragma unroll
        for (int nn = 0; nn < 4; nn++)
            #pragma unroll
            for (int e = 0; e < 4; e++) acc[mh][nn][e] = 0.0f;

    __syncthreads();

    const uint32_t tile0 = sbase + TILE_OFF;
    const uint32_t a_ldm = (uint32_t)((lane & 15) * ARSB + ((lane >> 4) << 4));
    const uint32_t a_st  = (uint32_t)(pxl * ARSB + aq * 16);
    const uint2* bbase = g_Bfrag + (size_t)(wid * 4) * 32 + lane;

    float2 q0[4], q1[4];

    auto ldg_wave = [&](int i, int w) {
        const int c0 = i * BK + aq * 8 + w * 4;
        #pragma unroll
        for (int e = 0; e < 4; e++) {
            const float* xp = xb + (size_t)(c0 + e) * HW;
            q0[e] = *reinterpret_cast<const float2*>(xp);
            q1[e] = *reinterpret_cast<const float2*>(xp + WW);
        }
    };
    // fire-and-forget L2 prefetch of a whole chunk's x (this thread's 8 ch x 2 rows);
    // warp coalescer dedups the 8-lanes-per-line sharing.
    auto pf_chunk = [&](int i) {
        const float* b = xb + (size_t)(i * BK + aq * 8) * HW;
        #pragma unroll
        for (int e = 0; e < 8; e++) {
            const float* p = b + (size_t)e * HW;
            PF_L2(p);
            PF_L2(p + WW);
        }
    };
    auto cvt_sts_wave = [&](int i, int w) {
        const int c0 = i * BK + aq * 8 + w * 4;
        float v[4];
        #pragma unroll
        for (int e = 0; e < 4; e++) {
            const float sc = s_scale[c0 + e], sh = s_shift[c0 + e];
            v[e] = 0.25f * (fmaxf(fmaf(q0[e].x, sc, sh), 0.0f)
                          + fmaxf(fmaf(q0[e].y, sc, sh), 0.0f)
                          + fmaxf(fmaf(q1[e].x, sc, sh), 0.0f)
                          + fmaxf(fmaf(q1[e].y, sc, sh), 0.0f));
        }
        const uint32_t st = tile0 + (uint32_t)((i & 1) * A_BYTES) + a_st + (uint32_t)(w * 8);
        sts64(st, pack2_f16(v[0], v[1]), pack2_f16(v[2], v[3]));
    };

    auto ldB = [&](int kc, uint2* dst) {
        const uint2* bp = bbase + (size_t)kc * (32 * 32);
        #pragma unroll
        for (int nn = 0; nn < 4; nn++) dst[nn] = __ldg(bp + nn * 32);
    };

    auto compute_ks = [&](int i, int ks, const uint2* bcur, uint2* bnxt, int kc_next) {
        const uint32_t aa = tile0 + (uint32_t)((i & 1) * A_BYTES) + a_ldm + (uint32_t)(ks * 32);
        uint32_t ah[4][4];
        #pragma unroll
        for (int mh = 0; mh < 4; mh++)
            LDMX4(ah[mh], aa + (uint32_t)(mh * 16 * ARSB));
        ldB(kc_next, bnxt);   // in flight under the MMAs below
        #pragma unroll
        for (int nn = 0; nn < 4; nn++) {
            #pragma unroll
            for (int mh = 0; mh < 4; mh++)
                MMA_F16(acc[mh][nn], ah[mh], bcur[nn].x, bcur[nn].y);
        }
    };

    // prologue: prefetch chunk 1, load chunk 0, B k-step 0
    uint2 bbuf0[4], bbuf1[4];
    pf_chunk(1);
    ldg_wave(0, 0); cvt_sts_wave(0, 0);
    ldg_wave(0, 1); cvt_sts_wave(0, 1);
    ldB(0, bbuf0);
    __syncthreads();

    #pragma unroll 1
    for (int i = 0; i < NCH; i++) {
        const bool more = (i + 1 < NCH);
        const int kc1 = i * 2 + 1;
        const int kc2 = more ? (i * 2 + 2) : 31;
        if (more) ldg_wave(i + 1, 0);
        if (i + 2 < NCH) pf_chunk(i + 2);        // fire-and-forget DRAM->L2
        compute_ks(i, 0, bbuf0, bbuf1, kc1);
        if (more) { cvt_sts_wave(i + 1, 0); ldg_wave(i + 1, 1); }
        compute_ks(i, 1, bbuf1, bbuf0, kc2);
        if (more) cvt_sts_wave(i + 1, 1);
        __syncthreads();
    }

    // epilogue: warp covers 64m x 32n
    const int fr = lane >> 2;
    const int q2 = (lane & 3) * 2;
    #pragma unroll
    for (int mh = 0; mh < 4; mh++) {
        #pragma unroll
        for (int half = 0; half < 2; half++) {
            const int m  = m0 + mh * 16 + fr + half * 8;
            const int im = m / PIX;
            const int px = m % PIX;
            float* ob = out + (size_t)im * (COUT * PIX) + px;
            #pragma unroll
            for (int nn = 0; nn < 4; nn++) {
                const int n = wid * 32 + nn * 8 + q2;
                ob[(size_t)n * PIX]       = acc[mh][nn][half * 2];
                ob[(size_t)(n + 1) * PIX] = acc[mh][nn][half * 2 + 1];
            }
        }
    }
}

extern "C" void kernel_launch(void* const* d_in, const int* in_sizes, int n_in,
                              void* d_out, int out_size)
{
    const float* x      = (const float*)d_in[0];
    const float* bn_w   = (const float*)d_in[1];
    const float* bn_b   = (const float*)d_in[2];
    const float* bn_m   = (const float*)d_in[3];
    const float* bn_v   = (const float*)d_in[4];
    const float* conv_w = (const float*)d_in[5];
    float* out = (float*)d_out;

    prepack_B<<<(BUNITS + 255) / 256, 256>>>(conv_w);

    cudaFuncSetAttribute(transition_hmma12_kernel,
                         cudaFuncAttributeMaxDynamicSharedMemorySize, SM_TOTAL);
    transition_hmma12_kernel<<<M_TOTAL / MT, 256, SM_TOTAL>>>(
        x, bn_w, bn_b, bn_m, bn_v, out);
}

// round 16
// speedup vs baseline: 1.4864x; 1.0633x over previous
#include <cuda_runtime.h>
#include <cuda_fp16.h>
#include <cstdint>

// TransitionLayer: BN(eval)+ReLU+1x1conv(512->256)+avgpool2x2, NCHW fp32.
// pool(conv(act)) == conv(pool(act)) -> GEMM M=50176, K=512, N=256.
// R16: WARP SPECIALIZATION. 512-thr CTA: warps 0-7 consumers (R15 consumer:
//      64m x 32n, B reg pipeline, 1-term fp16 HMMA), warps 8-15 producers
//      (x LDG -> BN/ReLU/pool -> fp16 STS) feeding a 4-stage A ring through
//      named barriers. Producers double-buffer a chunk in regs and run up to
//      4 chunks ahead -> sustained DRAM concurrency decoupled from MMA cadence.

#define BN_EPS 1e-5f

constexpr int CIN  = 512;
constexpr int HH   = 56;
constexpr int WW   = 56;
constexpr int HW   = HH * WW;           // 3136
constexpr int COUT = 256;
constexpr int PP   = 28;
constexpr int PIX  = PP * PP;           // 784
constexpr int M_TOTAL = 64 * PIX;       // 50176
constexpr int MT   = 64;
constexpr int BK   = 32;
constexpr int NCH  = CIN / BK;          // 16
constexpr int NSTG = 4;                 // A ring stages

// A fp16 tile: row = 64B data + 16B pad = 80B stride (conflict-free ldmatrix).
constexpr int ARSB    = 80;
constexpr int A_BYTES = MT * ARSB;      // 5120 per stage
constexpr int TILE_OFF = 4096;
constexpr int SM_TOTAL = TILE_OFF + NSTG * A_BYTES;   // 24576

// Prepacked B frags (fp16): [kc 32][nb 32][lane 32] -> uint2 {b0,b1}
constexpr int BUNITS = 32 * 32 * 32;
__device__ __align__(16) uint2 g_Bfrag[BUNITS];

#define MMA_F16(C, A, B0, B1)                                                \
    asm volatile("mma.sync.aligned.m16n8k16.row.col.f32.f16.f16.f32 "        \
                 "{%0,%1,%2,%3}, {%4,%5,%6,%7}, {%8,%9}, {%0,%1,%2,%3};"     \
                 : "+f"((C)[0]), "+f"((C)[1]), "+f"((C)[2]), "+f"((C)[3])    \
                 : "r"((A)[0]), "r"((A)[1]), "r"((A)[2]), "r"((A)[3]),       \
                   "r"(B0), "r"(B1))

#define LDMX4(R, ADDR)                                                       \
    asm volatile("ldmatrix.sync.aligned.m8n8.x4.shared.b16 {%0,%1,%2,%3}, [%4];" \
                 : "=r"((R)[0]), "=r"((R)[1]), "=r"((R)[2]), "=r"((R)[3])    \
                 : "r"(ADDR))

#define BAR_SYNC(id)   asm volatile("bar.sync %0, 512;"   :: "r"(id) : "memory")
#define BAR_ARRIVE(id) asm volatile("bar.arrive %0, 512;" :: "r"(id) : "memory")

__device__ __forceinline__ uint32_t smem_u32(const void* p) {
    uint32_t a;
    asm("{ .reg .u64 t; cvta.to.shared.u64 t, %1; cvt.u32.u64 %0, t; }" : "=r"(a) : "l"(p));
    return a;
}
__device__ __forceinline__ uint32_t pack2_f16(float v0, float v1) {
    __half h0 = __float2half_rn(v0);
    __half h1 = __float2half_rn(v1);
    return (uint32_t)__half_as_ushort(h0) | ((uint32_t)__half_as_ushort(h1) << 16);
}
__device__ __forceinline__ void sts64(uint32_t addr, uint32_t a, uint32_t b) {
    asm volatile("st.shared.v2.b32 [%0], {%1,%2};" :: "r"(addr), "r"(a), "r"(b) : "memory");
}

// ---------------- kernel 1: prepack B (fp16, fragment-major) ----------------
__global__ void prepack_B(const float* __restrict__ conv_w)
{
    const int idx = blockIdx.x * 256 + threadIdx.x;
    if (idx >= BUNITS) return;
    const int lane = idx & 31;
    const int nb   = (idx >> 5) & 31;
    const int kc   = idx >> 10;
    const int n  = nb * 8 + (lane >> 2);
    const int k0 = kc * 16 + (lane & 3) * 2;
    const float* wr = conv_w + (size_t)n * CIN;
    g_Bfrag[idx] = make_uint2(pack2_f16(wr[k0],     wr[k0 + 1]),
                              pack2_f16(wr[k0 + 8], wr[k0 + 9]));
}

// ---------------- kernel 2: main (warp-specialized) ----------------
__global__ __launch_bounds__(512, 1)
void transition_ws_kernel(const float* __restrict__ x,
                          const float* __restrict__ bn_w,
                          const float* __restrict__ bn_b,
                          const float* __restrict__ bn_m,
                          const float* __restrict__ bn_v,
                          float* __restrict__ out)
{
    extern __shared__ __align__(16) uint32_t sm[];
    float* s_scale = reinterpret_cast<float*>(sm);
    float* s_shift = reinterpret_cast<float*>(sm) + 512;
    const uint32_t sbase = smem_u32(sm);
    const uint32_t tile0 = sbase + TILE_OFF;

    const int tid  = threadIdx.x;
    const int wid  = tid >> 5;
    const int lane = tid & 31;
    const int m0   = blockIdx.x * MT;

    // BN tables: 512 threads, one channel each
    {
        const int c = tid;
        float inv = rsqrtf(bn_v[c] + BN_EPS);
        float sc  = bn_w[c] * inv;
        s_scale[c] = sc;
        s_shift[c] = bn_b[c] - bn_m[c] * sc;
    }
    __syncthreads();

    if (wid >= 8) {
        // ================= PRODUCER (warps 8..15, 256 threads) =================
        const int ptid = tid - 256;
        const int pxl  = ptid >> 2;        // pooled pixel 0..63
        const int aq   = ptid & 3;         // channels aq*8 .. +8
        const int mg   = m0 + pxl;
        const int img  = mg / PIX;
        const int pr   = mg % PIX;
        const float* xb = x + (size_t)img * (CIN * HW)
                            + (size_t)(2 * (pr / PP)) * WW + 2 * (pr % PP);
        const uint32_t a_st = (uint32_t)(pxl * ARSB + aq * 16);

        float2 a0[8], a1[8], b0[8], b1[8];   // double chunk buffer (64 regs)

        auto ldgA = [&](int i) {
            const int c0 = i * BK + aq * 8;
            #pragma unroll
            for (int e = 0; e < 8; e++) {
                const float* xp = xb + (size_t)(c0 + e) * HW;
                a0[e] = *reinterpret_cast<const float2*>(xp);
                a1[e] = *reinterpret_cast<const float2*>(xp + WW);
            }
        };
        auto ldgB = [&](int i) {
            const int c0 = i * BK + aq * 8;
            #pragma unroll
            for (int e = 0; e < 8; e++) {
                const float* xp = xb + (size_t)(c0 + e) * HW;
                b0[e] = *reinterpret_cast<const float2*>(xp);
                b1[e] = *reinterpret_cast<const float2*>(xp + WW);
            }
        };
        auto cvtsts = [&](int i, float2* r0, float2* r1) {
            const int c0 = i * BK + aq * 8;
            float v[8];
            #pragma unroll
            for (int e = 0; e < 8; e++) {
                const float sc = s_scale[c0 + e], sh = s_shift[c0 + e];
                v[e] = 0.25f * (fmaxf(fmaf(r0[e].x, sc, sh), 0.0f)
                              + fmaxf(fmaf(r0[e].y, sc, sh), 0.0f)
                              + fmaxf(fmaf(r1[e].x, sc, sh), 0.0f)
                              + fmaxf(fmaf(r1[e].y, sc, sh), 0.0f));
            }
            const uint32_t st = tile0 + (uint32_t)((i & (NSTG - 1)) * A_BYTES) + a_st;
            sts64(st,     pack2_f16(v[0], v[1]), pack2_f16(v[2], v[3]));
            sts64(st + 8, pack2_f16(v[4], v[5]), pack2_f16(v[6], v[7]));
        };

        ldgA(0);
        #pragma unroll 1
        for (int ip = 0; ip < NCH / 2; ip++) {
            const int i0 = 2 * ip, i1 = 2 * ip + 1;
            ldgB(i1);                                   // next chunk in flight
            if (i0 >= NSTG) BAR_SYNC(5 + (i0 & (NSTG - 1)));   // empty(i0)
            cvtsts(i0, a0, a1);
            BAR_ARRIVE(1 + (i0 & (NSTG - 1)));                 // full(i0)
            if (i1 + 1 < NCH) ldgA(i1 + 1);
            if (i1 >= NSTG) BAR_SYNC(5 + (i1 & (NSTG - 1)));   // empty(i1)
            cvtsts(i1, b0, b1);
            BAR_ARRIVE(1 + (i1 & (NSTG - 1)));                 // full(i1)
        }
        // producers done; exit
    } else {
        // ================= CONSUMER (warps 0..7, 256 threads) =================
        float acc[4][4][4];
        #pragma unroll
        for (int mh = 0; mh < 4; mh++)
            #pragma unroll
            for (int nn = 0; nn < 4; nn++)
                #pragma unroll
                for (int e = 0; e < 4; e++) acc[mh][nn][e] = 0.0f;

        const uint32_t a_ldm = (uint32_t)((lane & 15) * ARSB + ((lane >> 4) << 4));
        const uint2* bbase = g_Bfrag + (size_t)(wid * 4) * 32 + lane;

        auto ldB = [&](int kc, uint2* dst) {
            const uint2* bp = bbase + (size_t)kc * (32 * 32);
            #pragma unroll
            for (int nn = 0; nn < 4; nn++) dst[nn] = __ldg(bp + nn * 32);
        };
        auto compute_ks = [&](int i, int ks, const uint2* bcur, uint2* bnxt, int kc_next) {
            const uint32_t aa = tile0 + (uint32_t)((i & (NSTG - 1)) * A_BYTES)
                              + a_ldm + (uint32_t)(ks * 32);
            uint32_t ah[4][4];
            #pragma unroll
            for (int mh = 0; mh < 4; mh++)
                LDMX4(ah[mh], aa + (uint32_t)(mh * 16 * ARSB));
            ldB(kc_next, bnxt);
            #pragma unroll
            for (int nn = 0; nn < 4; nn++) {
                #pragma unroll
                for (int mh = 0; mh < 4; mh++)
                    MMA_F16(acc[mh][nn], ah[mh], bcur[nn].x, bcur[nn].y);
            }
        };

        uint2 bbuf0[4], bbuf1[4];
        ldB(0, bbuf0);

        #pragma unroll 1
        for (int i = 0; i < NCH; i++) {
            BAR_SYNC(1 + (i & (NSTG - 1)));            // wait full(i)
            const int kc1 = i * 2 + 1;
            const int kc2 = (i + 1 < NCH) ? (i * 2 + 2) : 31;
            compute_ks(i, 0, bbuf0, bbuf1, kc1);
            compute_ks(i, 1, bbuf1, bbuf0, kc2);
            if (i + NSTG < NCH)                        // balance: producer waits
                BAR_ARRIVE(5 + (i & (NSTG - 1)));      // empty(i) for chunks 0..11
        }

        // ---------- epilogue: warp covers 64m x 32n ----------
        const int fr = lane >> 2;
        const int q2 = (lane & 3) * 2;
        #pragma unroll
        for (int mh = 0; mh < 4; mh++) {
            #pragma unroll
            for (int half = 0; half < 2; half++) {
                const int m  = m0 + mh * 16 + fr + half * 8;
                const int im = m / PIX;
                const int px = m % PIX;
                float* ob = out + (size_t)im * (COUT * PIX) + px;
                #pragma unroll
                for (int nn = 0; nn < 4; nn++) {
                    const int n = wid * 32 + nn * 8 + q2;
                    ob[(size_t)n * PIX]       = acc[mh][nn][half * 2];
                    ob[(size_t)(n + 1) * PIX] = acc[mh][nn][half * 2 + 1];
                }
            }
        }
    }
}

extern "C" void kernel_launch(void* const* d_in, const int* in_sizes, int n_in,
                              void* d_out, int out_size)
{
    const float* x      = (const float*)d_in[0];
    const float* bn_w   = (const float*)d_in[1];
    const float* bn_b   = (const float*)d_in[2];
    const float* bn_m   = (const float*)d_in[3];
    const float* bn_v   = (const float*)d_in[4];
    const float* conv_w = (const float*)d_in[5];
    float* out = (float*)d_out;

    prepack_B<<<(BUNITS + 255) / 256, 256>>>(conv_w);

    cudaFuncSetAttribute(transition_ws_kernel,
                         cudaFuncAttributeMaxDynamicSharedMemorySize, SM_TOTAL);
    transition_ws_kernel<<<M_TOTAL / MT, 512, SM_TOTAL>>>(
        x, bn_w, bn_b, bn_m, bn_v, out);
}